// round 11
// baseline (speedup 1.0000x reference)
#include <cuda_runtime.h>

#define NATOMS   1500
#define NODE_DIM 128
#define HIDDEN   64
#define MUL1E    64
#define HID1E    32
#define NUM_BASIS 20
#define T        16      // edge tile side
#define NT       94      // ceil(1500/16)
#define ROWF     13500   // floats per output row: 1500*9
#define BSTRIDE  148     // padded row stride for transposed buffer (floats)

// Per-node packed data: a[3], b[3], coord[3], pad[3]  (48B = 3 x float4)
__device__ __align__(16) float g_node[NATOMS * 12];

__device__ __forceinline__ float silu_f(float d) {
    return d / (1.f + __expf(-d));
}

// One warp = one node; lanes own output columns (coalesced weight reads).
// lanes 0-15: role i (Wsi*/Wpi*), lanes 16-31: role j (Wsj*/Wpj*).
__global__ __launch_bounds__(256)
void node_kernel(
    const float* __restrict__ xs,   const float* __restrict__ xsph,
    const float* __restrict__ coord,
    const float* __restrict__ Wsi1, const float* __restrict__ Wsi2,
    const float* __restrict__ Wsj1, const float* __restrict__ Wsj2,
    const float* __restrict__ Wpi1, const float* __restrict__ Wpi2,
    const float* __restrict__ Wpj1, const float* __restrict__ Wpj2)
{
    int w    = threadIdx.x >> 5;
    int lane = threadIdx.x & 31;
    int n    = blockIdx.x * 8 + w;

    __shared__ __align__(16) float sx[8][NODE_DIM];
    __shared__ __align__(16) float sv[8][MUL1E * 3];

    // cooperative feature loads (all 256 threads, zero-pad invalid nodes)
    {
        int q = threadIdx.x;                       // sx: 8*32 = 256 float4
        int nn = blockIdx.x * 8 + (q >> 5);
        float4 val = make_float4(0.f, 0.f, 0.f, 0.f);
        if (nn < NATOMS) val = ((const float4*)(xs + (size_t)nn * NODE_DIM))[q & 31];
        ((float4*)sx)[q] = val;
    }
    for (int r = threadIdx.x; r < 8 * 48; r += 256) {   // sv: 8*48 float4
        int nn = blockIdx.x * 8 + r / 48;
        float4 val = make_float4(0.f, 0.f, 0.f, 0.f);
        if (nn < NATOMS) val = ((const float4*)(xsph + (size_t)nn * 480 + 128))[r % 48];
        ((float4*)sv)[r] = val;
    }
    __syncthreads();

    if (n >= NATOMS) return;    // warp-uniform

    bool roleI = (lane < 16);
    const float* xrow = sx[w];
    const float* vrow = sv[w];

    // ---- scalar MLP: 4 hidden cols per lane ----
    int c4 = (lane & 15) * 4;
    const float* W1 = roleI ? Wsi1 : Wsj1;
    const float* W2 = roleI ? Wsi2 : Wsj2;
    float a0 = 0.f, a1 = 0.f, a2 = 0.f, a3 = 0.f;
    #pragma unroll 8
    for (int f = 0; f < NODE_DIM; f++) {
        float xf = xrow[f];                               // broadcast LDS
        float4 wv = *(const float4*)(W1 + f * HIDDEN + c4);  // coalesced LDG.128
        a0 += xf * wv.x; a1 += xf * wv.y; a2 += xf * wv.z; a3 += xf * wv.w;
    }
    float4 w2v = *(const float4*)(W2 + c4);
    float s = silu_f(a0) * w2v.x + silu_f(a1) * w2v.y
            + silu_f(a2) * w2v.z + silu_f(a3) * w2v.w;
    #pragma unroll
    for (int off = 1; off < 16; off <<= 1) s += __shfl_xor_sync(0xffffffffu, s, off);
    // s = role sum on every lane of its half

    // ---- spherical MLP: 2 hidden cols per lane ----
    int c2 = (lane & 15) * 2;
    const float* P1 = roleI ? Wpi1 : Wpj1;
    const float* P2 = roleI ? Wpi2 : Wpj2;
    float h00 = 0.f, h01 = 0.f, h02 = 0.f;
    float h10 = 0.f, h11 = 0.f, h12 = 0.f;
    #pragma unroll 8
    for (int m = 0; m < MUL1E; m++) {
        float v0 = vrow[3 * m + 0], v1 = vrow[3 * m + 1], v2 = vrow[3 * m + 2];
        float2 pw = *(const float2*)(P1 + m * HID1E + c2);   // coalesced LDG.64
        h00 += v0 * pw.x; h01 += v1 * pw.x; h02 += v2 * pw.x;
        h10 += v0 * pw.y; h11 += v1 * pw.y; h12 += v2 * pw.y;
    }
    h00 *= 0.125f; h01 *= 0.125f; h02 *= 0.125f;    // / sqrt(64)
    h10 *= 0.125f; h11 *= 0.125f; h12 *= 0.125f;
    float2 p2v = *(const float2*)(P2 + c2);
    float n0 = sqrtf(h00 * h00 + h01 * h01 + h02 * h02);
    float n1 = sqrtf(h10 * h10 + h11 * h11 + h12 * h12);
    float wa = p2v.x / (1.f + __expf(-n0));          // W2 * sigmoid(|h|)
    float wb = p2v.y / (1.f + __expf(-n1));
    float o0 = h00 * wa + h10 * wb;
    float o1 = h01 * wa + h11 * wb;
    float o2 = h02 * wa + h12 * wb;
    #pragma unroll
    for (int off = 1; off < 16; off <<= 1) {
        o0 += __shfl_xor_sync(0xffffffffu, o0, off);
        o1 += __shfl_xor_sync(0xffffffffu, o1, off);
        o2 += __shfl_xor_sync(0xffffffffu, o2, off);
    }

    // pull role-j results to lane 0
    float sJ  = __shfl_sync(0xffffffffu, s,  16);
    float oj0 = __shfl_sync(0xffffffffu, o0, 16);
    float oj1 = __shfl_sync(0xffffffffu, o1, 16);
    float oj2 = __shfl_sync(0xffffffffu, o2, 16);

    if (lane == 0) {
        const float inv32 = 0.17677669529663689f;   // 1/sqrt(32)
        float fa = (1.f + s)  * inv32;
        float fb = (1.f + sJ) * inv32;
        float cx = coord[n * 3 + 0], cy = coord[n * 3 + 1], cz = coord[n * 3 + 2];
        float4* gp = (float4*)(g_node + n * 12);
        // e3nn (y,z,x) -> (x,y,z) permutation [2,0,1], fold in gate (1+s)
        gp[0] = make_float4(o2  * fa, o0  * fa, o1  * fa, oj2 * fb);
        gp[1] = make_float4(oj0 * fb, oj1 * fb, cx, cy);
        gp[2] = make_float4(cz, 0.f, 0.f, 0.f);
    }
}

// Symmetric 16x16 tiles over the upper triangle; dual-layout smem staging.
__global__ __launch_bounds__(256)
void edge_kernel(const float* __restrict__ Wrbf, float* __restrict__ out)
{
    int b = blockIdx.x;
    // triangular decode (once per block)
    int ti = (int)((2.f * NT + 1.f - sqrtf((2.f * NT + 1.f) * (2.f * NT + 1.f) - 8.f * (float)b)) * 0.5f);
    if (ti < 0) ti = 0; if (ti > NT - 1) ti = NT - 1;
    while (ti * NT - ti * (ti - 1) / 2 > b) ti--;
    while ((ti + 1) * NT - (ti + 1) * ti / 2 <= b) ti++;
    int tj = ti + (b - (ti * NT - ti * (ti - 1) / 2));

    int t  = threadIdx.x;
    int tx = t & 15;        // j within tile
    int ty = t >> 4;        // i within tile

    __shared__ __align__(16) float sbufA[T * T * 9];      // [ii][jj*9+c]
    __shared__ __align__(16) float sbufB[T * BSTRIDE];    // [jj][ii*9+cT]
    __shared__ __align__(16) float4 gi4[T][3];
    __shared__ __align__(16) float4 gj4[T][3];
    __shared__ float sWp[33];   // zero-padded: sWp[k+4] = W[k]

    if (t < 33) {
        int k = t - 4;
        sWp[t] = (k >= 0 && k < NUM_BASIS) ? Wrbf[k] : 0.f;
    }
    if (t >= 64 && t < 112) {
        int u = t - 64;
        int n = ti * T + u / 3;
        ((float4*)gi4)[u] = (n < NATOMS) ? ((const float4*)g_node)[n * 3 + u % 3]
                                         : make_float4(0.f, 0.f, 0.f, 0.f);
    }
    if (t >= 128 && t < 176) {
        int u = t - 128;
        int n = tj * T + u / 3;
        ((float4*)gj4)[u] = (n < NATOMS) ? ((const float4*)g_node)[n * 3 + u % 3]
                                         : make_float4(0.f, 0.f, 0.f, 0.f);
    }
    __syncthreads();

    int vi = NATOMS - ti * T; if (vi > T) vi = T;
    int vj = NATOMS - tj * T; if (vj > T) vj = T;
    bool offdiag = (ti != tj);

    if (ty < vi && tx < vj) {
        float4 i0 = gi4[ty][0], i1 = gi4[ty][1], i2 = gi4[ty][2];
        float4 j0 = gj4[tx][0], j1 = gj4[tx][1], j2 = gj4[tx][2];

        float dx = i1.z - j1.z, dy = i1.w - j1.w, dz = i2.x - j2.x;
        float d = sqrtf(dx * dx + dy * dy + dz * dz);

        const float delta = 5.0f / 19.0f;
        const float coeff = -0.5f / (delta * delta);
        int k0 = __float2int_rn(d * (19.0f / 5.0f));
        int k0c = min(k0, 24);
        float u0 = d - (float)(k0c - 4) * delta;   // u for kk=0
        float fc = 0.f;
        #pragma unroll
        for (int kk = 0; kk < 9; kk++) {
            float u = u0 - (float)kk * delta;
            fc += sWp[k0c + kk] * __expf(coeff * u * u);
        }
        float h = 0.5f * fc;

        float ai0 = i0.x * h, ai1 = i0.y * h, ai2 = i0.z * h;
        float bi0 = i0.w * h, bi1 = i1.x * h, bi2 = i1.y * h;
        float aj0 = j0.x, aj1 = j0.y, aj2 = j0.z;
        float bj0 = j0.w, bj1 = j1.x, bj2 = j1.y;

        float m00 = ai0 * bj0 + bi0 * aj0;
        float m01 = ai0 * bj1 + bi0 * aj1;
        float m02 = ai0 * bj2 + bi0 * aj2;
        float m10 = ai1 * bj0 + bi1 * aj0;
        float m11 = ai1 * bj1 + bi1 * aj1;
        float m12 = ai1 * bj2 + bi1 * aj2;
        float m20 = ai2 * bj0 + bi2 * aj0;
        float m21 = ai2 * bj1 + bi2 * aj1;
        float m22 = ai2 * bj2 + bi2 * aj2;

        float* a = sbufA + ty * (T * 9) + tx * 9;
        a[0] = m00; a[1] = m01; a[2] = m02;
        a[3] = m10; a[4] = m11; a[5] = m12;
        a[6] = m20; a[7] = m21; a[8] = m22;

        if (offdiag) {
            float* bq = sbufB + tx * BSTRIDE + ty * 9;
            bq[0] = m00; bq[1] = m10; bq[2] = m20;
            bq[3] = m01; bq[4] = m11; bq[5] = m21;
            bq[6] = m02; bq[7] = m12; bq[8] = m22;
        }
    }
    __syncthreads();

    if (ty < vi) {
        int w4 = (vj * 9) >> 2;
        const float4* src = (const float4*)(sbufA + ty * (T * 9));
        float4* dst = (float4*)(out + (size_t)(ti * T + ty) * ROWF + (size_t)tj * T * 9);
        #pragma unroll
        for (int c = tx; c < 36; c += 16)
            if (c < w4) dst[c] = src[c];
    }

    if (offdiag && ty < vj) {
        int w4 = (vi * 9) >> 2;
        const float4* src = (const float4*)(sbufB + ty * BSTRIDE);
        float4* dst = (float4*)(out + (size_t)(tj * T + ty) * ROWF + (size_t)ti * T * 9);
        #pragma unroll
        for (int c = tx; c < 36; c += 16)
            if (c < w4) dst[c] = src[c];
    }
}

extern "C" void kernel_launch(void* const* d_in, const int* in_sizes, int n_in,
                              void* d_out, int out_size)
{
    const float* xs    = (const float*)d_in[0];
    const float* xsph  = (const float*)d_in[1];
    const float* coord = (const float*)d_in[2];
    // d_in[3] = fc_edge_index (int32, full graph i-major) — structure fixed, unused
    const float* Wsi1 = (const float*)d_in[4];
    const float* Wsi2 = (const float*)d_in[5];
    const float* Wsj1 = (const float*)d_in[6];
    const float* Wsj2 = (const float*)d_in[7];
    const float* Wpi1 = (const float*)d_in[8];
    const float* Wpi2 = (const float*)d_in[9];
    const float* Wpj1 = (const float*)d_in[10];
    const float* Wpj2 = (const float*)d_in[11];
    const float* Wrbf = (const float*)d_in[12];
    float* out = (float*)d_out;

    node_kernel<<<(NATOMS + 7) / 8, 256>>>(xs, xsph, coord,
                                           Wsi1, Wsi2, Wsj1, Wsj2,
                                           Wpi1, Wpi2, Wpj1, Wpj2);

    int nblocks = NT * (NT + 1) / 2;   // 4465 upper-triangle tiles
    edge_kernel<<<nblocks, 256>>>(Wrbf, out);
}

// round 12
// speedup vs baseline: 1.5979x; 1.5979x over previous
#include <cuda_runtime.h>

#define NATOMS   1500
#define NODE_DIM 128
#define HIDDEN   64
#define MUL1E    64
#define HID1E    32
#define NUM_BASIS 20
#define T        16      // edge tile side
#define NT       94      // ceil(1500/16)
#define ROWF     13500   // floats per output row: 1500*9
#define BSTRIDE  148     // padded row stride for transposed buffer (floats)
#define TABN     8192    // fc table entries
#define TABSCALE 256.0f  // entries per unit distance (range [0,32])

// Per-node packed data: a[3], b[3], coord[3], pad[3]  (48B = 3 x float4)
__device__ __align__(16) float g_node[NATOMS * 12];
// fc lookup: g_tab[k] = (0.5*fc(k/256), 0.5*fc((k+1)/256))
__device__ __align__(8) float2 g_tab[TABN];

__device__ __forceinline__ float fc_full(float d, const float* __restrict__ Wrbf)
{
    const float delta = 5.0f / 19.0f;
    const float coeff = -0.5f / (delta * delta);
    float fc = 0.f;
    #pragma unroll
    for (int k = 0; k < NUM_BASIS; k++) {
        float u = d - (float)k * delta;
        fc += Wrbf[k] * __expf(coeff * u * u);
    }
    return fc;
}

__global__ void node_kernel(
    const float* __restrict__ xs,   const float* __restrict__ xsph,
    const float* __restrict__ coord,
    const float* __restrict__ Wsi1, const float* __restrict__ Wsi2,
    const float* __restrict__ Wsj1, const float* __restrict__ Wsj2,
    const float* __restrict__ Wpi1, const float* __restrict__ Wpi2,
    const float* __restrict__ Wpj1, const float* __restrict__ Wpj2,
    const float* __restrict__ Wrbf)
{
    int n = blockIdx.x;
    int t = threadIdx.x;
    int lane = t & 31;
    int wid = t >> 5;
    __shared__ float sx[NODE_DIM];
    __shared__ float sv[MUL1E * 3];
    __shared__ float red[4];        // per-warp scalar partials
    __shared__ float soi[3], soj[3];

    // blocks 0..31 also build the fc table (2 entries per thread)
    if (n < 32) {
        #pragma unroll
        for (int e = 0; e < 2; e++) {
            int k = n * 256 + t + e * 128;
            float d0 = (float)k / TABSCALE;
            float d1 = (float)(k + 1) / TABSCALE;
            g_tab[k] = make_float2(0.5f * fc_full(d0, Wrbf),
                                   0.5f * fc_full(d1, Wrbf));
        }
    }

    sx[t] = xs[n * NODE_DIM + t];
    const float* vp = xsph + n * 480 + 128;   // 1e block [64,3]
    for (int k = t; k < MUL1E * 3; k += 128) sv[k] = vp[k];
    __syncthreads();

    // ---- scalar MLPs: silu(x@W1)@W2.  threads 0..63 -> i-role, 64..127 -> j-role
    {
        const float* W1 = (t < 64) ? Wsi1 : Wsj1;
        const float* W2 = (t < 64) ? Wsi2 : Wsj2;
        int h = t & 63;
        float d = 0.f;
        #pragma unroll 16
        for (int f = 0; f < NODE_DIM; f++) d += sx[f] * W1[f * HIDDEN + h];
        float s = d / (1.f + __expf(-d));     // silu
        float v = s * W2[h];
        #pragma unroll
        for (int off = 16; off > 0; off >>= 1) v += __shfl_down_sync(0xffffffffu, v, off);
        if (lane == 0) red[wid] = v;
    }

    // ---- spherical MLPs: warp 0 -> i-role, warp 1 -> j-role (one lane per hidden h)
    if (t < 64) {
        const float* W1 = (t < 32) ? Wpi1 : Wpj1;
        const float* W2 = (t < 32) ? Wpi2 : Wpj2;
        int h = lane;
        float h0 = 0.f, h1 = 0.f, h2 = 0.f;
        #pragma unroll 16
        for (int m = 0; m < MUL1E; m++) {
            float w = W1[m * HID1E + h];
            h0 += sv[m * 3 + 0] * w;
            h1 += sv[m * 3 + 1] * w;
            h2 += sv[m * 3 + 2] * w;
        }
        h0 *= 0.125f; h1 *= 0.125f; h2 *= 0.125f;   // / sqrt(64)
        float nrm = sqrtf(h0 * h0 + h1 * h1 + h2 * h2);
        float gate = 1.f / (1.f + __expf(-nrm));    // sigmoid(|h|)
        float w2 = W2[h] * gate;
        float o0 = h0 * w2, o1 = h1 * w2, o2 = h2 * w2;
        #pragma unroll
        for (int off = 16; off > 0; off >>= 1) {
            o0 += __shfl_down_sync(0xffffffffu, o0, off);
            o1 += __shfl_down_sync(0xffffffffu, o1, off);
            o2 += __shfl_down_sync(0xffffffffu, o2, off);
        }
        if (lane == 0) {
            float* dst = (t < 32) ? soi : soj;
            dst[0] = o0; dst[1] = o1; dst[2] = o2;
        }
    }
    __syncthreads();

    if (t == 0) {
        const float inv32 = 0.17677669529663689f;   // 1/sqrt(32)
        float fa = (1.f + red[0] + red[1]) * inv32;
        float fb = (1.f + red[2] + red[3]) * inv32;
        float* gp = g_node + n * 12;
        // e3nn (y,z,x) -> (x,y,z) permutation [2,0,1], fold in gate (1+s)
        gp[0] = soi[2] * fa;  gp[1] = soi[0] * fa;  gp[2] = soi[1] * fa;
        gp[3] = soj[2] * fb;  gp[4] = soj[0] * fb;  gp[5] = soj[1] * fb;
        gp[6] = coord[n*3+0]; gp[7] = coord[n*3+1]; gp[8] = coord[n*3+2];
        gp[9] = 0.f; gp[10] = 0.f; gp[11] = 0.f;
    }
}

// Symmetric 16x16 tiles over the upper triangle; dual-layout smem staging;
// fc via table lookup + lerp.
__global__ __launch_bounds__(256)
void edge_kernel(float* __restrict__ out)
{
    int b = blockIdx.x;
    // triangular decode (once per block)
    int ti = (int)((2.f * NT + 1.f - sqrtf((2.f * NT + 1.f) * (2.f * NT + 1.f) - 8.f * (float)b)) * 0.5f);
    if (ti < 0) ti = 0; if (ti > NT - 1) ti = NT - 1;
    while (ti * NT - ti * (ti - 1) / 2 > b) ti--;
    while ((ti + 1) * NT - (ti + 1) * ti / 2 <= b) ti++;
    int tj = ti + (b - (ti * NT - ti * (ti - 1) / 2));

    int t  = threadIdx.x;
    int tx = t & 15;        // j within tile
    int ty = t >> 4;        // i within tile

    __shared__ __align__(16) float sbufA[T * T * 9];      // [ii][jj*9+c]
    __shared__ __align__(16) float sbufB[T * BSTRIDE];    // [jj][ii*9+cT]
    __shared__ __align__(16) float4 gi4[T][3];
    __shared__ __align__(16) float4 gj4[T][3];

    if (t >= 64 && t < 112) {
        int u = t - 64;
        int n = ti * T + u / 3;
        ((float4*)gi4)[u] = (n < NATOMS) ? ((const float4*)g_node)[n * 3 + u % 3]
                                         : make_float4(0.f, 0.f, 0.f, 0.f);
    }
    if (t >= 128 && t < 176) {
        int u = t - 128;
        int n = tj * T + u / 3;
        ((float4*)gj4)[u] = (n < NATOMS) ? ((const float4*)g_node)[n * 3 + u % 3]
                                         : make_float4(0.f, 0.f, 0.f, 0.f);
    }
    __syncthreads();

    int vi = NATOMS - ti * T; if (vi > T) vi = T;
    int vj = NATOMS - tj * T; if (vj > T) vj = T;
    bool offdiag = (ti != tj);

    if (ty < vi && tx < vj) {
        float4 i0 = gi4[ty][0], i1 = gi4[ty][1], i2 = gi4[ty][2];
        float4 j0 = gj4[tx][0], j1 = gj4[tx][1], j2 = gj4[tx][2];

        float dx = i1.z - j1.z, dy = i1.w - j1.w, dz = i2.x - j2.x;
        float d = sqrtf(dx * dx + dy * dy + dz * dz);

        // table lookup + lerp: h = 0.5*fc(d)
        float u = d * TABSCALE;
        int k = (int)u;
        if (k > TABN - 1) k = TABN - 1;
        float frac = u - (float)k;
        float2 g = g_tab[k];
        float h = g.x + frac * (g.y - g.x);

        float ai0 = i0.x * h, ai1 = i0.y * h, ai2 = i0.z * h;
        float bi0 = i0.w * h, bi1 = i1.x * h, bi2 = i1.y * h;
        float aj0 = j0.x, aj1 = j0.y, aj2 = j0.z;
        float bj0 = j0.w, bj1 = j1.x, bj2 = j1.y;

        float m00 = ai0 * bj0 + bi0 * aj0;
        float m01 = ai0 * bj1 + bi0 * aj1;
        float m02 = ai0 * bj2 + bi0 * aj2;
        float m10 = ai1 * bj0 + bi1 * aj0;
        float m11 = ai1 * bj1 + bi1 * aj1;
        float m12 = ai1 * bj2 + bi1 * aj2;
        float m20 = ai2 * bj0 + bi2 * aj0;
        float m21 = ai2 * bj1 + bi2 * aj1;
        float m22 = ai2 * bj2 + bi2 * aj2;

        float* a = sbufA + ty * (T * 9) + tx * 9;
        a[0] = m00; a[1] = m01; a[2] = m02;
        a[3] = m10; a[4] = m11; a[5] = m12;
        a[6] = m20; a[7] = m21; a[8] = m22;

        if (offdiag) {
            float* bq = sbufB + tx * BSTRIDE + ty * 9;
            bq[0] = m00; bq[1] = m10; bq[2] = m20;
            bq[3] = m01; bq[4] = m11; bq[5] = m21;
            bq[6] = m02; bq[7] = m12; bq[8] = m22;
        }
    }
    __syncthreads();

    if (ty < vi) {
        int w4 = (vj * 9) >> 2;
        const float4* src = (const float4*)(sbufA + ty * (T * 9));
        float4* dst = (float4*)(out + (size_t)(ti * T + ty) * ROWF + (size_t)tj * T * 9);
        #pragma unroll
        for (int c = tx; c < 36; c += 16)
            if (c < w4) dst[c] = src[c];
    }

    if (offdiag && ty < vj) {
        int w4 = (vi * 9) >> 2;
        const float4* src = (const float4*)(sbufB + ty * BSTRIDE);
        float4* dst = (float4*)(out + (size_t)(tj * T + ty) * ROWF + (size_t)ti * T * 9);
        #pragma unroll
        for (int c = tx; c < 36; c += 16)
            if (c < w4) dst[c] = src[c];
    }
}

extern "C" void kernel_launch(void* const* d_in, const int* in_sizes, int n_in,
                              void* d_out, int out_size)
{
    const float* xs    = (const float*)d_in[0];
    const float* xsph  = (const float*)d_in[1];
    const float* coord = (const float*)d_in[2];
    // d_in[3] = fc_edge_index (int32, full graph i-major) — structure fixed, unused
    const float* Wsi1 = (const float*)d_in[4];
    const float* Wsi2 = (const float*)d_in[5];
    const float* Wsj1 = (const float*)d_in[6];
    const float* Wsj2 = (const float*)d_in[7];
    const float* Wpi1 = (const float*)d_in[8];
    const float* Wpi2 = (const float*)d_in[9];
    const float* Wpj1 = (const float*)d_in[10];
    const float* Wpj2 = (const float*)d_in[11];
    const float* Wrbf = (const float*)d_in[12];
    float* out = (float*)d_out;

    node_kernel<<<NATOMS, 128>>>(xs, xsph, coord,
                                 Wsi1, Wsi2, Wsj1, Wsj2,
                                 Wpi1, Wpi2, Wpj1, Wpj2, Wrbf);

    int nblocks = NT * (NT + 1) / 2;   // 4465 upper-triangle tiles
    edge_kernel<<<nblocks, 256>>>(out);
}

// round 14
// speedup vs baseline: 1.7159x; 1.0738x over previous
#include <cuda_runtime.h>

#define NATOMS   1500
#define NODE_DIM 128
#define HIDDEN   64
#define MUL1E    64
#define HID1E    32
#define NUM_BASIS 20
#define T        16      // edge tile side
#define NT       94      // ceil(1500/16)
#define ROWF     13500   // floats per output row: 1500*9
#define BSTRIDE  148     // padded row stride for transposed buffer (floats)
#define TABN     832     // fc table entries: [0, 6.5] step 1/128
#define TABSCALE 128.0f

// Per-node packed data: a[3], b[3], coord[3], pad[3]  (48B = 3 x float4)
__device__ __align__(16) float g_node[NATOMS * 12];
// fc lookup: g_tab[k] = (0.5*fc(k/128), 0.5*fc((k+1)/128))
__device__ __align__(8) float2 g_tab[TABN];

__device__ __forceinline__ float fc_full(float d, const float* __restrict__ Wrbf)
{
    const float delta = 5.0f / 19.0f;
    const float coeff = -0.5f / (delta * delta);
    float fc = 0.f;
    #pragma unroll
    for (int k = 0; k < NUM_BASIS; k++) {
        float u = d - (float)k * delta;
        fc += Wrbf[k] * __expf(coeff * u * u);
    }
    return fc;
}

__global__ void node_kernel(
    const float* __restrict__ xs,   const float* __restrict__ xsph,
    const float* __restrict__ coord,
    const float* __restrict__ Wsi1, const float* __restrict__ Wsi2,
    const float* __restrict__ Wsj1, const float* __restrict__ Wsj2,
    const float* __restrict__ Wpi1, const float* __restrict__ Wpi2,
    const float* __restrict__ Wpj1, const float* __restrict__ Wpj2,
    const float* __restrict__ Wrbf)
{
    int n = blockIdx.x;
    int t = threadIdx.x;
    int lane = t & 31;
    int wid = t >> 5;
    __shared__ float sx[NODE_DIM];
    __shared__ float sv[MUL1E * 3];
    __shared__ float red[4];        // per-warp scalar partials
    __shared__ float soi[3], soj[3];

    // blocks 0..6 build the fc table (1 entry per thread)
    if (n < 7) {
        int k = n * 128 + t;
        if (k < TABN) {
            float d0 = (float)k / TABSCALE;
            float d1 = (float)(k + 1) / TABSCALE;
            g_tab[k] = make_float2(0.5f * fc_full(d0, Wrbf),
                                   0.5f * fc_full(d1, Wrbf));
        }
    }

    sx[t] = xs[n * NODE_DIM + t];
    const float* vp = xsph + n * 480 + 128;   // 1e block [64,3]
    for (int k = t; k < MUL1E * 3; k += 128) sv[k] = vp[k];
    __syncthreads();

    // ---- scalar MLPs: silu(x@W1)@W2.  threads 0..63 -> i-role, 64..127 -> j-role
    {
        const float* W1 = (t < 64) ? Wsi1 : Wsj1;
        const float* W2 = (t < 64) ? Wsi2 : Wsj2;
        int h = t & 63;
        float d = 0.f;
        #pragma unroll 16
        for (int f = 0; f < NODE_DIM; f++) d += sx[f] * W1[f * HIDDEN + h];
        float s = d / (1.f + __expf(-d));     // silu
        float v = s * W2[h];
        #pragma unroll
        for (int off = 16; off > 0; off >>= 1) v += __shfl_down_sync(0xffffffffu, v, off);
        if (lane == 0) red[wid] = v;
    }

    // ---- spherical MLPs: warp 0 -> i-role, warp 1 -> j-role (one lane per hidden h)
    if (t < 64) {
        const float* W1 = (t < 32) ? Wpi1 : Wpj1;
        const float* W2 = (t < 32) ? Wpi2 : Wpj2;
        int h = lane;
        float h0 = 0.f, h1 = 0.f, h2 = 0.f;
        #pragma unroll 16
        for (int m = 0; m < MUL1E; m++) {
            float w = W1[m * HID1E + h];
            h0 += sv[m * 3 + 0] * w;
            h1 += sv[m * 3 + 1] * w;
            h2 += sv[m * 3 + 2] * w;
        }
        h0 *= 0.125f; h1 *= 0.125f; h2 *= 0.125f;   // / sqrt(64)
        float nrm = sqrtf(h0 * h0 + h1 * h1 + h2 * h2);
        float gate = 1.f / (1.f + __expf(-nrm));    // sigmoid(|h|)
        float w2 = W2[h] * gate;
        float o0 = h0 * w2, o1 = h1 * w2, o2 = h2 * w2;
        #pragma unroll
        for (int off = 16; off > 0; off >>= 1) {
            o0 += __shfl_down_sync(0xffffffffu, o0, off);
            o1 += __shfl_down_sync(0xffffffffu, o1, off);
            o2 += __shfl_down_sync(0xffffffffu, o2, off);
        }
        if (lane == 0) {
            float* dst = (t < 32) ? soi : soj;
            dst[0] = o0; dst[1] = o1; dst[2] = o2;
        }
    }
    __syncthreads();

    if (t == 0) {
        const float inv32 = 0.17677669529663689f;   // 1/sqrt(32)
        float fa = (1.f + red[0] + red[1]) * inv32;
        float fb = (1.f + red[2] + red[3]) * inv32;
        float* gp = g_node + n * 12;
        // e3nn (y,z,x) -> (x,y,z) permutation [2,0,1], fold in gate (1+s)
        gp[0] = soi[2] * fa;  gp[1] = soi[0] * fa;  gp[2] = soi[1] * fa;
        gp[3] = soj[2] * fb;  gp[4] = soj[0] * fb;  gp[5] = soj[1] * fb;
        gp[6] = coord[n*3+0]; gp[7] = coord[n*3+1]; gp[8] = coord[n*3+2];
        gp[9] = 0.f; gp[10] = 0.f; gp[11] = 0.f;
    }
}

// Symmetric 16x16 tiles over the upper triangle; dual-layout smem staging;
// fc via SHARED-memory table lookup + lerp.
__global__ __launch_bounds__(256)
void edge_kernel(float* __restrict__ out)
{
    int b = blockIdx.x;
    // triangular decode (once per block)
    int ti = (int)((2.f * NT + 1.f - sqrtf((2.f * NT + 1.f) * (2.f * NT + 1.f) - 8.f * (float)b)) * 0.5f);
    if (ti < 0) ti = 0; if (ti > NT - 1) ti = NT - 1;
    while (ti * NT - ti * (ti - 1) / 2 > b) ti--;
    while ((ti + 1) * NT - (ti + 1) * ti / 2 <= b) ti++;
    int tj = ti + (b - (ti * NT - ti * (ti - 1) / 2));

    int t  = threadIdx.x;
    int tx = t & 15;        // j within tile
    int ty = t >> 4;        // i within tile

    __shared__ __align__(16) float sbufA[T * T * 9];      // [ii][jj*9+c]
    __shared__ __align__(16) float sbufB[T * BSTRIDE];    // [jj][ii*9+cT]
    __shared__ __align__(16) float4 gi4[T][3];
    __shared__ __align__(16) float4 gj4[T][3];
    __shared__ __align__(8)  float2 stab[TABN];

    // copy fc table into smem (coalesced)
    #pragma unroll
    for (int q = t; q < TABN; q += 256) stab[q] = g_tab[q];

    if (t >= 64 && t < 112) {
        int u = t - 64;
        int n = ti * T + u / 3;
        ((float4*)gi4)[u] = (n < NATOMS) ? ((const float4*)g_node)[n * 3 + u % 3]
                                         : make_float4(0.f, 0.f, 0.f, 0.f);
    }
    if (t >= 128 && t < 176) {
        int u = t - 128;
        int n = tj * T + u / 3;
        ((float4*)gj4)[u] = (n < NATOMS) ? ((const float4*)g_node)[n * 3 + u % 3]
                                         : make_float4(0.f, 0.f, 0.f, 0.f);
    }
    __syncthreads();

    int vi = NATOMS - ti * T; if (vi > T) vi = T;
    int vj = NATOMS - tj * T; if (vj > T) vj = T;
    bool offdiag = (ti != tj);

    if (ty < vi && tx < vj) {
        float4 i0 = gi4[ty][0], i1 = gi4[ty][1], i2 = gi4[ty][2];
        float4 j0 = gj4[tx][0], j1 = gj4[tx][1], j2 = gj4[tx][2];

        float dx = i1.z - j1.z, dy = i1.w - j1.w, dz = i2.x - j2.x;
        float d = sqrtf(dx * dx + dy * dy + dz * dz);

        // smem table lookup + lerp: h = 0.5*fc(d); d beyond table -> 0
        float u = d * TABSCALE;
        int k = (int)u;
        float h = 0.f;
        if (k < TABN) {
            float frac = u - (float)k;
            float2 g = stab[k];
            h = g.x + frac * (g.y - g.x);
        }

        float ai0 = i0.x * h, ai1 = i0.y * h, ai2 = i0.z * h;
        float bi0 = i0.w * h, bi1 = i1.x * h, bi2 = i1.y * h;
        float aj0 = j0.x, aj1 = j0.y, aj2 = j0.z;
        float bj0 = j0.w, bj1 = j1.x, bj2 = j1.y;

        float m00 = ai0 * bj0 + bi0 * aj0;
        float m01 = ai0 * bj1 + bi0 * aj1;
        float m02 = ai0 * bj2 + bi0 * aj2;
        float m10 = ai1 * bj0 + bi1 * aj0;
        float m11 = ai1 * bj1 + bi1 * aj1;
        float m12 = ai1 * bj2 + bi1 * aj2;
        float m20 = ai2 * bj0 + bi2 * aj0;
        float m21 = ai2 * bj1 + bi2 * aj1;
        float m22 = ai2 * bj2 + bi2 * aj2;

        float* a = sbufA + ty * (T * 9) + tx * 9;
        a[0] = m00; a[1] = m01; a[2] = m02;
        a[3] = m10; a[4] = m11; a[5] = m12;
        a[6] = m20; a[7] = m21; a[8] = m22;

        if (offdiag) {
            float* bq = sbufB + tx * BSTRIDE + ty * 9;
            bq[0] = m00; bq[1] = m10; bq[2] = m20;
            bq[3] = m01; bq[4] = m11; bq[5] = m21;
            bq[6] = m02; bq[7] = m12; bq[8] = m22;
        }
    }
    __syncthreads();

    if (ty < vi) {
        int w4 = (vj * 9) >> 2;
        const float4* src = (const float4*)(sbufA + ty * (T * 9));
        float4* dst = (float4*)(out + (size_t)(ti * T + ty) * ROWF + (size_t)tj * T * 9);
        #pragma unroll
        for (int c = tx; c < 36; c += 16)
            if (c < w4) dst[c] = src[c];
    }

    if (offdiag && ty < vj) {
        int w4 = (vi * 9) >> 2;
        const float4* src = (const float4*)(sbufB + ty * BSTRIDE);
        float4* dst = (float4*)(out + (size_t)(tj * T + ty) * ROWF + (size_t)ti * T * 9);
        #pragma unroll
        for (int c = tx; c < 36; c += 16)
            if (c < w4) dst[c] = src[c];
    }
}

extern "C" void kernel_launch(void* const* d_in, const int* in_sizes, int n_in,
                              void* d_out, int out_size)
{
    const float* xs    = (const float*)d_in[0];
    const float* xsph  = (const float*)d_in[1];
    const float* coord = (const float*)d_in[2];
    // d_in[3] = fc_edge_index (int32, full graph i-major) — structure fixed, unused
    const float* Wsi1 = (const float*)d_in[4];
    const float* Wsi2 = (const float*)d_in[5];
    const float* Wsj1 = (const float*)d_in[6];
    const float* Wsj2 = (const float*)d_in[7];
    const float* Wpi1 = (const float*)d_in[8];
    const float* Wpi2 = (const float*)d_in[9];
    const float* Wpj1 = (const float*)d_in[10];
    const float* Wpj2 = (const float*)d_in[11];
    const float* Wrbf = (const float*)d_in[12];
    float* out = (float*)d_out;

    node_kernel<<<NATOMS, 128>>>(xs, xsph, coord,
                                 Wsi1, Wsi2, Wsj1, Wsj2,
                                 Wpi1, Wpi2, Wpj1, Wpj2, Wrbf);

    int nblocks = NT * (NT + 1) / 2;   // 4465 upper-triangle tiles
    edge_kernel<<<nblocks, 256>>>(out);
}

// round 15
// speedup vs baseline: 1.8364x; 1.0703x over previous
#include <cuda_runtime.h>

#define NATOMS   1500
#define NODE_DIM 128
#define HIDDEN   64
#define MUL1E    64
#define HID1E    32
#define NUM_BASIS 20
#define T        16      // edge tile side
#define NT       94      // ceil(1500/16)
#define ROWF     13500   // floats per output row: 1500*9
#define BSTRIDE  148     // padded row stride for transposed buffer (floats)

// Per-node packed data: a[3], b[3], coord[3], pad[3]  (48B = 3 x float4)
__device__ __align__(16) float g_node[NATOMS * 12];

__device__ __forceinline__ float silu_f(float d) {
    return d / (1.f + __expf(-d));
}

// One block = one node; one warp per task:
//   warp 0: scalar MLP role i   warp 1: scalar MLP role j
//   warp 2: spherical MLP role i  warp 3: spherical MLP role j
__global__ __launch_bounds__(128)
void node_kernel(
    const float* __restrict__ xs,   const float* __restrict__ xsph,
    const float* __restrict__ coord,
    const float* __restrict__ Wsi1, const float* __restrict__ Wsi2,
    const float* __restrict__ Wsj1, const float* __restrict__ Wsj2,
    const float* __restrict__ Wpi1, const float* __restrict__ Wpi2,
    const float* __restrict__ Wpj1, const float* __restrict__ Wpj2)
{
    int n = blockIdx.x;
    int t = threadIdx.x;
    int lane = t & 31;
    int w = t >> 5;

    __shared__ __align__(16) float4 sx4[NODE_DIM / 4];   // x features
    __shared__ __align__(16) float4 sv4[MUL1E];          // 1e vectors, padded (v0,v1,v2,0)
    __shared__ float sS[2];          // scalar role sums
    __shared__ float sO[2][3];       // spherical role sums

    // load x (threads 0..31, one LDG.128 each)
    if (t < 32) sx4[t] = ((const float4*)(xs + (size_t)n * NODE_DIM))[t];
    // load 1e block into padded float4 (threads 0..63, m = t)
    if (t < 64) {
        const float* vp = xsph + (size_t)n * 480 + 128 + 3 * t;
        sv4[t] = make_float4(vp[0], vp[1], vp[2], 0.f);
    }
    __syncthreads();

    if (w < 2) {
        // ---- scalar MLP, role = w. lane owns h = 2*lane, 2*lane+1 ----
        const float* W1 = w ? Wsj1 : Wsi1;
        const float* W2 = w ? Wsj2 : Wsi2;
        float a0 = 0.f, a1 = 0.f;
        #pragma unroll 8
        for (int f4 = 0; f4 < 32; f4++) {
            float4 x = sx4[f4];                      // LDS.128 broadcast
            float2 w0 = *(const float2*)(W1 + (f4 * 4 + 0) * HIDDEN + 2 * lane);
            float2 w1 = *(const float2*)(W1 + (f4 * 4 + 1) * HIDDEN + 2 * lane);
            float2 w2 = *(const float2*)(W1 + (f4 * 4 + 2) * HIDDEN + 2 * lane);
            float2 w3 = *(const float2*)(W1 + (f4 * 4 + 3) * HIDDEN + 2 * lane);
            a0 += x.x * w0.x + x.y * w1.x + x.z * w2.x + x.w * w3.x;
            a1 += x.x * w0.y + x.y * w1.y + x.z * w2.y + x.w * w3.y;
        }
        float2 w2v = *(const float2*)(W2 + 2 * lane);
        float v = silu_f(a0) * w2v.x + silu_f(a1) * w2v.y;
        #pragma unroll
        for (int off = 1; off < 32; off <<= 1) v += __shfl_xor_sync(0xffffffffu, v, off);
        if (lane == 0) sS[w] = v;
    } else {
        // ---- spherical MLP, role = w-2. lane owns hidden h = lane ----
        int r = w - 2;
        const float* P1 = r ? Wpj1 : Wpi1;
        const float* P2 = r ? Wpj2 : Wpi2;
        float h0 = 0.f, h1 = 0.f, h2 = 0.f;
        #pragma unroll 8
        for (int m = 0; m < MUL1E; m++) {
            float4 vv = sv4[m];                      // LDS.128 broadcast
            float pw = P1[m * HID1E + lane];         // coalesced LDG.32
            h0 += vv.x * pw; h1 += vv.y * pw; h2 += vv.z * pw;
        }
        h0 *= 0.125f; h1 *= 0.125f; h2 *= 0.125f;    // / sqrt(64)
        float nrm = sqrtf(h0 * h0 + h1 * h1 + h2 * h2);
        float wg = P2[lane] / (1.f + __expf(-nrm));  // W2 * sigmoid(|h|)
        float o0 = h0 * wg, o1 = h1 * wg, o2 = h2 * wg;
        #pragma unroll
        for (int off = 1; off < 32; off <<= 1) {
            o0 += __shfl_xor_sync(0xffffffffu, o0, off);
            o1 += __shfl_xor_sync(0xffffffffu, o1, off);
            o2 += __shfl_xor_sync(0xffffffffu, o2, off);
        }
        if (lane == 0) { sO[r][0] = o0; sO[r][1] = o1; sO[r][2] = o2; }
    }
    __syncthreads();

    if (t == 0) {
        const float inv32 = 0.17677669529663689f;    // 1/sqrt(32)
        float fa = (1.f + sS[0]) * inv32;
        float fb = (1.f + sS[1]) * inv32;
        float cx = coord[n * 3 + 0], cy = coord[n * 3 + 1], cz = coord[n * 3 + 2];
        float4* gp = (float4*)(g_node + n * 12);
        // e3nn (y,z,x) -> (x,y,z) permutation [2,0,1], fold in gate (1+s)
        gp[0] = make_float4(sO[0][2] * fa, sO[0][0] * fa, sO[0][1] * fa, sO[1][2] * fb);
        gp[1] = make_float4(sO[1][0] * fb, sO[1][1] * fb, cx, cy);
        gp[2] = make_float4(cz, 0.f, 0.f, 0.f);
    }
}

// Symmetric 16x16 tiles over the upper triangle; dual-layout smem staging;
// fc via 9-term windowed expf sum (R8, measured best).
__global__ __launch_bounds__(256)
void edge_kernel(const float* __restrict__ Wrbf, float* __restrict__ out)
{
    int b = blockIdx.x;
    // triangular decode (once per block)
    int ti = (int)((2.f * NT + 1.f - sqrtf((2.f * NT + 1.f) * (2.f * NT + 1.f) - 8.f * (float)b)) * 0.5f);
    if (ti < 0) ti = 0; if (ti > NT - 1) ti = NT - 1;
    while (ti * NT - ti * (ti - 1) / 2 > b) ti--;
    while ((ti + 1) * NT - (ti + 1) * ti / 2 <= b) ti++;
    int tj = ti + (b - (ti * NT - ti * (ti - 1) / 2));

    int t  = threadIdx.x;
    int tx = t & 15;        // j within tile
    int ty = t >> 4;        // i within tile

    __shared__ __align__(16) float sbufA[T * T * 9];      // [ii][jj*9+c]
    __shared__ __align__(16) float sbufB[T * BSTRIDE];    // [jj][ii*9+cT]
    __shared__ __align__(16) float4 gi4[T][3];
    __shared__ __align__(16) float4 gj4[T][3];
    __shared__ float sWp[33];   // zero-padded: sWp[k+4] = W[k]

    if (t < 33) {
        int k = t - 4;
        sWp[t] = (k >= 0 && k < NUM_BASIS) ? Wrbf[k] : 0.f;
    }
    if (t >= 64 && t < 112) {
        int u = t - 64;
        int n = ti * T + u / 3;
        ((float4*)gi4)[u] = (n < NATOMS) ? ((const float4*)g_node)[n * 3 + u % 3]
                                         : make_float4(0.f, 0.f, 0.f, 0.f);
    }
    if (t >= 128 && t < 176) {
        int u = t - 128;
        int n = tj * T + u / 3;
        ((float4*)gj4)[u] = (n < NATOMS) ? ((const float4*)g_node)[n * 3 + u % 3]
                                         : make_float4(0.f, 0.f, 0.f, 0.f);
    }
    __syncthreads();

    int vi = NATOMS - ti * T; if (vi > T) vi = T;
    int vj = NATOMS - tj * T; if (vj > T) vj = T;
    bool offdiag = (ti != tj);

    if (ty < vi && tx < vj) {
        float4 i0 = gi4[ty][0], i1 = gi4[ty][1], i2 = gi4[ty][2];
        float4 j0 = gj4[tx][0], j1 = gj4[tx][1], j2 = gj4[tx][2];

        float dx = i1.z - j1.z, dy = i1.w - j1.w, dz = i2.x - j2.x;
        float d = sqrtf(dx * dx + dy * dy + dz * dz);

        const float delta = 5.0f / 19.0f;
        const float coeff = -0.5f / (delta * delta);
        int k0 = __float2int_rn(d * (19.0f / 5.0f));
        int k0c = min(k0, 24);
        float u0 = d - (float)(k0c - 4) * delta;   // u for kk=0
        float fc = 0.f;
        #pragma unroll
        for (int kk = 0; kk < 9; kk++) {
            float u = u0 - (float)kk * delta;
            fc += sWp[k0c + kk] * __expf(coeff * u * u);
        }
        float h = 0.5f * fc;

        float ai0 = i0.x * h, ai1 = i0.y * h, ai2 = i0.z * h;
        float bi0 = i0.w * h, bi1 = i1.x * h, bi2 = i1.y * h;
        float aj0 = j0.x, aj1 = j0.y, aj2 = j0.z;
        float bj0 = j0.w, bj1 = j1.x, bj2 = j1.y;

        float m00 = ai0 * bj0 + bi0 * aj0;
        float m01 = ai0 * bj1 + bi0 * aj1;
        float m02 = ai0 * bj2 + bi0 * aj2;
        float m10 = ai1 * bj0 + bi1 * aj0;
        float m11 = ai1 * bj1 + bi1 * aj1;
        float m12 = ai1 * bj2 + bi1 * aj2;
        float m20 = ai2 * bj0 + bi2 * aj0;
        float m21 = ai2 * bj1 + bi2 * aj1;
        float m22 = ai2 * bj2 + bi2 * aj2;

        float* a = sbufA + ty * (T * 9) + tx * 9;
        a[0] = m00; a[1] = m01; a[2] = m02;
        a[3] = m10; a[4] = m11; a[5] = m12;
        a[6] = m20; a[7] = m21; a[8] = m22;

        if (offdiag) {
            float* bq = sbufB + tx * BSTRIDE + ty * 9;
            bq[0] = m00; bq[1] = m10; bq[2] = m20;
            bq[3] = m01; bq[4] = m11; bq[5] = m21;
            bq[6] = m02; bq[7] = m12; bq[8] = m22;
        }
    }
    __syncthreads();

    if (ty < vi) {
        int w4 = (vj * 9) >> 2;
        const float4* src = (const float4*)(sbufA + ty * (T * 9));
        float4* dst = (float4*)(out + (size_t)(ti * T + ty) * ROWF + (size_t)tj * T * 9);
        #pragma unroll
        for (int c = tx; c < 36; c += 16)
            if (c < w4) dst[c] = src[c];
    }

    if (offdiag && ty < vj) {
        int w4 = (vi * 9) >> 2;
        const float4* src = (const float4*)(sbufB + ty * BSTRIDE);
        float4* dst = (float4*)(out + (size_t)(tj * T + ty) * ROWF + (size_t)ti * T * 9);
        #pragma unroll
        for (int c = tx; c < 36; c += 16)
            if (c < w4) dst[c] = src[c];
    }
}

extern "C" void kernel_launch(void* const* d_in, const int* in_sizes, int n_in,
                              void* d_out, int out_size)
{
    const float* xs    = (const float*)d_in[0];
    const float* xsph  = (const float*)d_in[1];
    const float* coord = (const float*)d_in[2];
    // d_in[3] = fc_edge_index (int32, full graph i-major) — structure fixed, unused
    const float* Wsi1 = (const float*)d_in[4];
    const float* Wsi2 = (const float*)d_in[5];
    const float* Wsj1 = (const float*)d_in[6];
    const float* Wsj2 = (const float*)d_in[7];
    const float* Wpi1 = (const float*)d_in[8];
    const float* Wpi2 = (const float*)d_in[9];
    const float* Wpj1 = (const float*)d_in[10];
    const float* Wpj2 = (const float*)d_in[11];
    const float* Wrbf = (const float*)d_in[12];
    float* out = (float*)d_out;

    node_kernel<<<NATOMS, 128>>>(xs, xsph, coord,
                                 Wsi1, Wsi2, Wsj1, Wsj2,
                                 Wpi1, Wpi2, Wpj1, Wpj2);

    int nblocks = NT * (NT + 1) / 2;   // 4465 upper-triangle tiles
    edge_kernel<<<nblocks, 256>>>(Wrbf, out);
}